// round 6
// baseline (speedup 1.0000x reference)
#include <cuda_runtime.h>
#include <cstdint>

// DecisionTree: out[b, j] = prod_f softmax((x[b,f]*W + cumsum_bias[f]) / 0.1)[digit_f(j)]
// out = (4096, 16384) fp32 = 256 MiB. Store-bound (~7.1 TB/s effective writes achieved).
// R6: grid 16384 (4 CTAs/row). Per-WARP 2KB smem staging + per-warp cp.async.bulk store.
//     One block barrier total; warps fill + issue TMA independently.

#define FF 7
#define OUT4_PER_ROW 4096           // float4s per row
#define SEGS 4                      // CTAs per row
#define WARP_F4 128                 // float4s per warp slice (2 KB)

__global__ __launch_bounds__(256, 8)
void dt_kernel(const float* __restrict__ x,
               const float* __restrict__ cut,
               float* __restrict__ out) {
    __shared__ float bins[FF][4];
    __shared__ __align__(16) float4 seg_buf[1024];   // 16 KB: 8 warps x 2 KB

    const int bid  = blockIdx.x;
    const int row  = bid >> 2;      // bid / SEGS
    const int seg  = bid & 3;       // bid % SEGS
    const int t    = threadIdx.x;
    const int w    = t >> 5;
    const int lane = t & 31;

    // --- per-feature softmax bins (threads 0..6) ---
    if (t < FF) {
        float c0 = cut[t * 3 + 0];
        float c1 = cut[t * 3 + 1];
        float c2 = cut[t * 3 + 2];
        float lo = fminf(c0, c1), hi = fmaxf(c0, c1);
        float s0 = fminf(lo, c2);
        float s2 = fmaxf(hi, c2);
        float s1 = (c0 + c1 + c2) - s0 - s2;
        float b1 = -s0;
        float b2 = b1 - s1;
        float b3 = b2 - s2;

        float xv = x[row * FF + t];
        float h0 = xv * 10.0f;
        float h1 = (xv * 2.0f + b1) * 10.0f;
        float h2 = (xv * 3.0f + b2) * 10.0f;
        float h3 = (xv * 4.0f + b3) * 10.0f;
        float m  = fmaxf(fmaxf(h0, h1), fmaxf(h2, h3));
        float e0 = __expf(h0 - m);
        float e1 = __expf(h1 - m);
        float e2 = __expf(h2 - m);
        float e3 = __expf(h3 - m);
        float inv = 1.0f / (e0 + e1 + e2 + e3);
        bins[t][0] = e0 * inv;
        bins[t][1] = e1 * inv;
        bins[t][2] = e2 * inv;
        bins[t][3] = e3 * inv;
    }
    __syncthreads();   // the only block barrier

    // Warp w owns segment-local float4 range [w*128, w*128+128).
    // Within-row float4 index g = seg*1024 + w*128 + lane*4 + q.
    // i (digits d0,d1) = seg*4 + (w>>1);  t_scalar = (w&1)*128 + lane*4 + q.
    // d2 = (w&1)*2 + (lane>>4), d3 = (lane>>2)&3, d4 = lane&3, d5 = q, d6 = c.
    const int i = seg * 4 + (w >> 1);
    float h = bins[0][i >> 2] * bins[1][i & 3];
    float common = h
                 * bins[2][((w & 1) << 1) | (lane >> 4)]
                 * bins[3][(lane >> 2) & 3]
                 * bins[4][lane & 3];
    float v60 = bins[6][0], v61 = bins[6][1], v62 = bins[6][2], v63 = bins[6][3];

    float4* wbuf = seg_buf + w * WARP_F4;
#pragma unroll
    for (int q = 0; q < 4; q++) {
        float p = common * bins[5][q];
        float4 val;
        val.x = p * v60;
        val.y = p * v61;
        val.z = p * v62;
        val.w = p * v63;
        wbuf[lane * 4 + q] = val;
    }

    // Order shared writes before async-proxy read, sync the warp, then lane 0
    // issues this warp's 2 KB bulk store.
    asm volatile("fence.proxy.async.shared::cta;" ::: "memory");
    __syncwarp();
    if (lane == 0) {
        uint32_t saddr;
        asm("{ .reg .u64 tmp; cvta.to.shared.u64 tmp, %1; cvt.u32.u64 %0, tmp; }"
            : "=r"(saddr) : "l"(wbuf));
        float4* gdst = reinterpret_cast<float4*>(out) +
                       (size_t)row * OUT4_PER_ROW + (size_t)seg * 1024 + (size_t)w * WARP_F4;
        asm volatile(
            "cp.async.bulk.global.shared::cta.bulk_group [%0], [%1], %2;\n\t"
            "cp.async.bulk.commit_group;\n\t"
            "cp.async.bulk.wait_group.read 0;\n\t"
            :: "l"(gdst), "r"(saddr), "n"(WARP_F4 * 16)
            : "memory");
    }
}

extern "C" void kernel_launch(void* const* d_in, const int* in_sizes, int n_in,
                              void* d_out, int out_size) {
    const float* x   = (const float*)d_in[0];        // (4096, 7)
    const float* cut = (const float*)d_in[1];        // (7, 3)
    float* out = (float*)d_out;                      // (4096, 16384)
    dt_kernel<<<4096 * SEGS, 256>>>(x, cut, out);
}

// round 7
// speedup vs baseline: 1.0707x; 1.0707x over previous
#include <cuda_runtime.h>

// DecisionTree: out[b, j] = prod_f softmax((x[b,f]*W + cumsum_bias[f]) / 0.1)[digit_f(j)]
// out = (4096, 16384) fp32 = 256 MiB. Store-bound: STG and TMA variants both converge
// to ~7.1 TB/s effective writes -> L2->DRAM drain is the ceiling.
// R7: harness-best R2 shape (SEGS=4, grid 16384, STG.128 + __stcs) with the second
//     __syncthreads and head[] smem removed (head product recomputed per thread).

#define FF 7
#define OUT4_PER_ROW 4096           // float4s per row
#define SEGS 4                      // CTAs per row
#define ITERS 4                     // 16 head-iterations / SEGS

__global__ __launch_bounds__(256, 8)
void dt_kernel(const float* __restrict__ x,
               const float* __restrict__ cut,
               float* __restrict__ out) {
    __shared__ float bins[FF][4];

    const int bid = blockIdx.x;
    const int row = bid >> 2;       // bid / SEGS
    const int seg = bid & 3;        // bid % SEGS
    const int t   = threadIdx.x;

    // --- per-feature softmax bins (threads 0..6) ---
    if (t < FF) {
        float c0 = cut[t * 3 + 0];
        float c1 = cut[t * 3 + 1];
        float c2 = cut[t * 3 + 2];
        // sort 3 values ascending
        float lo = fminf(c0, c1), hi = fmaxf(c0, c1);
        float s0 = fminf(lo, c2);
        float s2 = fmaxf(hi, c2);
        float s1 = (c0 + c1 + c2) - s0 - s2;
        // cumulative biases: b0=0, b1=-s0, b2=-s0-s1, b3=-s0-s1-s2
        float b1 = -s0;
        float b2 = b1 - s1;
        float b3 = b2 - s2;

        float xv = x[row * FF + t];
        float h0 = xv * 10.0f;
        float h1 = (xv * 2.0f + b1) * 10.0f;
        float h2 = (xv * 3.0f + b2) * 10.0f;
        float h3 = (xv * 4.0f + b3) * 10.0f;
        float m  = fmaxf(fmaxf(h0, h1), fmaxf(h2, h3));
        float e0 = __expf(h0 - m);
        float e1 = __expf(h1 - m);
        float e2 = __expf(h2 - m);
        float e3 = __expf(h3 - m);
        float inv = 1.0f / (e0 + e1 + e2 + e3);
        bins[t][0] = e0 * inv;
        bins[t][1] = e1 * inv;
        bins[t][2] = e2 * inv;
        bins[t][3] = e3 * inv;
    }
    __syncthreads();   // the only block barrier

    // --- tail product: features 2..5 from thread index, feature 6 in float4 lanes ---
    float tail = bins[2][(t >> 6) & 3] * bins[3][(t >> 4) & 3]
               * bins[4][(t >> 2) & 3] * bins[5][t & 3];
    float4 v;
    v.x = tail * bins[6][0];
    v.y = tail * bins[6][1];
    v.z = tail * bins[6][2];
    v.w = tail * bins[6][3];

    // j = (i*256 + t)*4 + c ; i = seg*ITERS + k encodes digits d0,d1.
    // Head product bins[0][i>>2]*bins[1][i&3] recomputed per thread (no smem, no 2nd sync).
    float4* o4 = reinterpret_cast<float4*>(out) + (size_t)row * OUT4_PER_ROW + t;
#pragma unroll
    for (int k = 0; k < ITERS; k++) {
        int i = seg * ITERS + k;
        float h = bins[0][i >> 2] * bins[1][i & 3];
        float4 w;
        w.x = h * v.x;
        w.y = h * v.y;
        w.z = h * v.z;
        w.w = h * v.w;
        __stcs(&o4[i * 256], w);
    }
}

extern "C" void kernel_launch(void* const* d_in, const int* in_sizes, int n_in,
                              void* d_out, int out_size) {
    const float* x   = (const float*)d_in[0];        // (4096, 7)
    const float* cut = (const float*)d_in[1];        // (7, 3)
    float* out = (float*)d_out;                      // (4096, 16384)
    dt_kernel<<<4096 * SEGS, 256>>>(x, cut, out);
}

// round 8
// speedup vs baseline: 1.1103x; 1.0370x over previous
#include <cuda_runtime.h>

// DecisionTree: out[b, j] = prod_f softmax((x[b,f]*W + cumsum_bias[f]) / 0.1)[digit_f(j)]
// B=4096, F=7, D=3 -> 4 bins/feature, out = (4096, 16384) fp32 = 256 MiB. Store-bound.
// R8 = R2 (empirically best: 38.1us ncu / 39.4us harness, ~7.1 TB/s effective writes):
//   grid 16384 (4 CTAs/row), head[] smem, coalesced STG.128 with __stcs streaming hint.

#define FF 7
#define OUT4_PER_ROW 4096           // float4s per row
#define SEGS 4                      // CTAs per row
#define ITERS 4                     // 16 head-iterations / SEGS

__global__ __launch_bounds__(256, 8)
void dt_kernel(const float* __restrict__ x,
               const float* __restrict__ cut,
               float* __restrict__ out) {
    __shared__ float bins[FF][4];
    __shared__ float head[16];

    const int bid = blockIdx.x;
    const int row = bid >> 2;       // bid / SEGS
    const int seg = bid & 3;        // bid % SEGS
    const int t   = threadIdx.x;

    // --- per-feature softmax bins (threads 0..6) ---
    if (t < FF) {
        float c0 = cut[t * 3 + 0];
        float c1 = cut[t * 3 + 1];
        float c2 = cut[t * 3 + 2];
        // sort 3 values ascending
        float lo = fminf(c0, c1), hi = fmaxf(c0, c1);
        float s0 = fminf(lo, c2);
        float s2 = fmaxf(hi, c2);
        float s1 = (c0 + c1 + c2) - s0 - s2;
        // cumulative biases: b0=0, b1=-s0, b2=-s0-s1, b3=-s0-s1-s2
        float b1 = -s0;
        float b2 = b1 - s1;
        float b3 = b2 - s2;

        float xv = x[row * FF + t];
        float h0 = xv * 10.0f;
        float h1 = (xv * 2.0f + b1) * 10.0f;
        float h2 = (xv * 3.0f + b2) * 10.0f;
        float h3 = (xv * 4.0f + b3) * 10.0f;
        float m  = fmaxf(fmaxf(h0, h1), fmaxf(h2, h3));
        float e0 = __expf(h0 - m);
        float e1 = __expf(h1 - m);
        float e2 = __expf(h2 - m);
        float e3 = __expf(h3 - m);
        float inv = 1.0f / (e0 + e1 + e2 + e3);
        bins[t][0] = e0 * inv;
        bins[t][1] = e1 * inv;
        bins[t][2] = e2 * inv;
        bins[t][3] = e3 * inv;
    }
    __syncthreads();

    // --- head products over features 0,1 (16 combos) ---
    if (t < 16) {
        head[t] = bins[0][t >> 2] * bins[1][t & 3];
    }

    // --- tail product: features 2..5 from thread index, feature 6 in float4 lanes ---
    float tail = bins[2][(t >> 6) & 3] * bins[3][(t >> 4) & 3]
               * bins[4][(t >> 2) & 3] * bins[5][t & 3];
    float4 v;
    v.x = tail * bins[6][0];
    v.y = tail * bins[6][1];
    v.z = tail * bins[6][2];
    v.w = tail * bins[6][3];
    __syncthreads();

    // j = (i*256 + t)*4 + c ; i = seg*ITERS + k encodes digits d0,d1.
    float4* o4 = reinterpret_cast<float4*>(out) + (size_t)row * OUT4_PER_ROW + t;
#pragma unroll
    for (int k = 0; k < ITERS; k++) {
        int i = seg * ITERS + k;
        float h = head[i];
        float4 w;
        w.x = h * v.x;
        w.y = h * v.y;
        w.z = h * v.z;
        w.w = h * v.w;
        __stcs(&o4[i * 256], w);
    }
}

extern "C" void kernel_launch(void* const* d_in, const int* in_sizes, int n_in,
                              void* d_out, int out_size) {
    const float* x   = (const float*)d_in[0];        // (4096, 7)
    const float* cut = (const float*)d_in[1];        // (7, 3)
    float* out = (float*)d_out;                      // (4096, 16384)
    dt_kernel<<<4096 * SEGS, 256>>>(x, cut, out);
}